// round 6
// baseline (speedup 1.0000x reference)
#include <cuda_runtime.h>
#include <cuda_fp16.h>
#include <cstdint>

#define MAXN 100000
#define MAXE 1600000
#define EPS_LN 1e-5f

typedef unsigned long long u64;
typedef unsigned int u32;

// ---------------- scratch (device globals; no allocation allowed) ----------
__device__ int    g_degi[MAXN];
__device__ int    g_off[MAXN + 1];
__device__ int    g_cursor[MAXN];
__device__ int    g_csr[MAXE];
__device__ float  g_rdeg[MAXN];
__device__ float  g_agg[(size_t)MAXN * 128];
__device__ float  g_hA[(size_t)MAXN * 128];
__device__ float  g_hB[(size_t)MAXN * 128];
__device__ __half g_xh[(size_t)MAXN * 128];    // half mirror of x
__device__ __half g_h0h[(size_t)MAXN * 128];   // half mirror of h0
__device__ __half g_t2h[(size_t)MAXN * 64];    // half mirror of t2 cols [64,128)
__device__ float  g_Bw0[256 * 128];            // [k][n] tf32-rounded concat weights
__device__ float  g_Bw1[256 * 128];
__device__ float  g_Bw2[128 * 128];

// ---------------- helpers ---------------------------------------------------
__device__ __forceinline__ float tf32r(float f) {
    uint32_t u;
    asm("cvt.rna.tf32.f32 %0, %1;" : "=r"(u) : "f"(f));
    return __uint_as_float(u);
}
__device__ __forceinline__ uint32_t smem_u32(const void* p) {
    uint32_t a;
    asm("{ .reg .u64 t; cvta.to.shared.u64 t, %1; cvt.u32.u64 %0, t; }" : "=r"(a) : "l"(p));
    return a;
}
__device__ __forceinline__ void cp_async16(uint32_t dst, const void* src) {
    asm volatile("cp.async.ca.shared.global [%0], [%1], 16;" :: "r"(dst), "l"(src));
}
__device__ __forceinline__ void cp_commit() {
    asm volatile("cp.async.commit_group;" ::: "memory");
}
__device__ __forceinline__ void cp_wait0() {
    asm volatile("cp.async.wait_group 0;" ::: "memory");
}
__device__ __forceinline__ void mma_tf32(float* c, const u32* a, const u32* b) {
    asm volatile(
        "mma.sync.aligned.m16n8k8.row.col.f32.tf32.tf32.f32 "
        "{%0,%1,%2,%3}, {%4,%5,%6,%7}, {%8,%9}, {%0,%1,%2,%3};"
        : "+f"(c[0]), "+f"(c[1]), "+f"(c[2]), "+f"(c[3])
        : "r"(a[0]), "r"(a[1]), "r"(a[2]), "r"(a[3]), "r"(b[0]), "r"(b[1]));
}
// accumulate 4 halves (packed uint2) into float4
__device__ __forceinline__ void acc_h4(float4& a, uint2 p) {
    float2 lo = __half22float2(*reinterpret_cast<__half2*>(&p.x));
    float2 hi = __half22float2(*reinterpret_cast<__half2*>(&p.y));
    a.x += lo.x; a.y += lo.y; a.z += hi.x; a.w += hi.y;
}
__device__ __forceinline__ uint2 f4_to_h4(float4 v) {
    uint2 r;
    __half2 lo = __floats2half2_rn(v.x, v.y);
    __half2 hi = __floats2half2_rn(v.z, v.w);
    r.x = *reinterpret_cast<u32*>(&lo);
    r.y = *reinterpret_cast<u32*>(&hi);
    return r;
}

// ---------------- CSR build --------------------------------------------------
__global__ void k_zeroi(int* __restrict__ p, int n) {
    int i = blockIdx.x * blockDim.x + threadIdx.x;
    if (i < n) p[i] = 0;
}

__global__ void k_count(const int* __restrict__ dst, int* __restrict__ deg, int E) {
    int i = blockIdx.x * blockDim.x + threadIdx.x;
    if (i < E) atomicAdd(&deg[dst[i]], 1);
}

__global__ void __launch_bounds__(1024) k_scan(
    const int* __restrict__ deg, int* __restrict__ off,
    int* __restrict__ cursor, float* __restrict__ rdeg, int n)
{
    __shared__ int sb[1024];
    int tid = threadIdx.x;
    int chunk = (n + 1023) >> 10;
    int s = tid * chunk;
    int e = min(s + chunk, n);
    int sum = 0;
    for (int i = s; i < e; i++) sum += deg[i];
    sb[tid] = sum;
    __syncthreads();
    int val = sum;
    for (int o = 1; o < 1024; o <<= 1) {
        int t = (tid >= o) ? sb[tid - o] : 0;
        __syncthreads();
        sb[tid] += t;
        __syncthreads();
    }
    int base = sb[tid] - val;
    for (int i = s; i < e; i++) {
        int d = deg[i];
        off[i] = base;
        cursor[i] = base;
        rdeg[i] = 1.0f / fmaxf((float)d, 1.0f);
        base += d;
    }
    if (tid == 1023) off[n] = base;
}

__global__ void k_fill(const int* __restrict__ src, const int* __restrict__ dst,
                       int* __restrict__ cursor, int* __restrict__ csr, int E)
{
    int i = blockIdx.x * blockDim.x + threadIdx.x;
    if (i < E) {
        int p = atomicAdd(&cursor[dst[i]], 1);
        csr[p] = src[i];
    }
}

// ---------------- weight prep + x->half -------------------------------------
__global__ void k_prep01(const float* __restrict__ Wr, const float* __restrict__ Wn,
                         float* __restrict__ Bw)
{
    int i = blockIdx.x * blockDim.x + threadIdx.x;
    if (i < 256 * 128) {
        int k = i >> 7, nn = i & 127;
        float v = (k < 128) ? Wr[k * 128 + nn] : Wn[(k - 128) * 128 + nn];
        Bw[i] = tf32r(v);
    }
}

__global__ void k_prep2(const float* __restrict__ Wr2, const float* __restrict__ Wn2,
                        float* __restrict__ Bw)
{
    int i = blockIdx.x * blockDim.x + threadIdx.x;
    if (i < 128 * 128) {
        int k = i >> 7, nn = i & 127;
        float v = (nn < 64) ? Wr2[k * 64 + nn] : Wn2[k * 64 + (nn - 64)];
        Bw[i] = tf32r(v);
    }
}

__global__ void k_cvt_half(const float* __restrict__ src, __half* __restrict__ dst, long n4) {
    long i = blockIdx.x * (long)blockDim.x + threadIdx.x;
    for (; i < n4; i += (long)gridDim.x * blockDim.x) {
        float4 v = reinterpret_cast<const float4*>(src)[i];
        reinterpret_cast<uint2*>(dst)[i] = f4_to_h4(v);
    }
}

// ---------------- gather-based mean aggregation (half features) ------------
__global__ void __launch_bounds__(256) k_agg128h(
    const __half* __restrict__ feat, const int* __restrict__ csr,
    const int* __restrict__ off, const float* __restrict__ rdeg,
    float* __restrict__ agg, int n)
{
    int w = (blockIdx.x * 256 + threadIdx.x) >> 5;
    int lane = threadIdx.x & 31;
    if (w >= n) return;
    int s0 = off[w], s1 = off[w + 1];
    float4 a0 = make_float4(0.f, 0.f, 0.f, 0.f);
    float4 a1 = make_float4(0.f, 0.f, 0.f, 0.f);
    float4 a2 = make_float4(0.f, 0.f, 0.f, 0.f);
    float4 a3 = make_float4(0.f, 0.f, 0.f, 0.f);
    int e = s0;
    for (; e + 4 <= s1; e += 4) {
        int i0 = csr[e], i1 = csr[e + 1], i2 = csr[e + 2], i3 = csr[e + 3];
        uint2 v0 = *reinterpret_cast<const uint2*>(feat + (size_t)i0 * 128 + lane * 4);
        uint2 v1 = *reinterpret_cast<const uint2*>(feat + (size_t)i1 * 128 + lane * 4);
        uint2 v2 = *reinterpret_cast<const uint2*>(feat + (size_t)i2 * 128 + lane * 4);
        uint2 v3 = *reinterpret_cast<const uint2*>(feat + (size_t)i3 * 128 + lane * 4);
        acc_h4(a0, v0); acc_h4(a1, v1); acc_h4(a2, v2); acc_h4(a3, v3);
    }
    for (; e < s1; e++) {
        int i0 = csr[e];
        uint2 v0 = *reinterpret_cast<const uint2*>(feat + (size_t)i0 * 128 + lane * 4);
        acc_h4(a0, v0);
    }
    float r = rdeg[w];
    float4 o4;
    o4.x = ((a0.x + a1.x) + (a2.x + a3.x)) * r;
    o4.y = ((a0.y + a1.y) + (a2.y + a3.y)) * r;
    o4.z = ((a0.z + a1.z) + (a2.z + a3.z)) * r;
    o4.w = ((a0.w + a1.w) + (a2.w + a3.w)) * r;
    *reinterpret_cast<float4*>(agg + (size_t)w * 128 + lane * 4) = o4;
}

// 64-wide mean agg over half mirror of t2 cols [64,128); half-warp per stream
__global__ void __launch_bounds__(256) k_agg64h(
    const __half* __restrict__ t2h, const int* __restrict__ csr,
    const int* __restrict__ off, const float* __restrict__ rdeg,
    float* __restrict__ agg, int n)
{
    int w = (blockIdx.x * 256 + threadIdx.x) >> 5;
    int lane = threadIdx.x & 31;
    if (w >= n) return;
    int half = lane >> 4, l = lane & 15;
    int s0 = off[w], s1 = off[w + 1];
    float4 a = make_float4(0.f, 0.f, 0.f, 0.f);
    float4 b = make_float4(0.f, 0.f, 0.f, 0.f);
    int e = s0 + half;
    for (; e + 2 < s1; e += 4) {
        int i0 = csr[e], i1 = csr[e + 2];
        uint2 v0 = *reinterpret_cast<const uint2*>(t2h + (size_t)i0 * 64 + l * 4);
        uint2 v1 = *reinterpret_cast<const uint2*>(t2h + (size_t)i1 * 64 + l * 4);
        acc_h4(a, v0); acc_h4(b, v1);
    }
    if (e < s1) {
        int i0 = csr[e];
        uint2 v0 = *reinterpret_cast<const uint2*>(t2h + (size_t)i0 * 64 + l * 4);
        acc_h4(a, v0);
    }
    a.x += b.x; a.y += b.y; a.z += b.z; a.w += b.w;
    a.x += __shfl_xor_sync(0xffffffffu, a.x, 16);
    a.y += __shfl_xor_sync(0xffffffffu, a.y, 16);
    a.z += __shfl_xor_sync(0xffffffffu, a.z, 16);
    a.w += __shfl_xor_sync(0xffffffffu, a.w, 16);
    if (half == 0) {
        float r = rdeg[w];
        float4 o4 = make_float4(a.x * r, a.y * r, a.z * r, a.w * r);
        *reinterpret_cast<float4*>(agg + (size_t)w * 64 + l * 4) = o4;
    }
}

// ---------------- tf32 mma.sync GEMM + fused bias/LN/ReLU + half mirror ----
// CTA tile 128x128, 8 warps (4 in M x 2 in N), warp tile 32x64, BK=32.
// HMODE: 0 none, 1 full 128-col half mirror, 2 half mirror of cols [64,128)
#define S_AS0 0
#define S_AS1 18432
#define S_BS0 36864
#define S_BS1 54272
#define S_BIAS 71680
#define S_GAM  72192
#define S_BET  72704
#define S_MU   73216
#define S_RS   73728
#define S_TOTAL 74240

template<int KTOT, bool DO_LN, int HMODE>
__global__ void __launch_bounds__(256) k_gemm_mma(
    const float* __restrict__ X, const float* __restrict__ AGG,
    const float* __restrict__ Bw, const float* __restrict__ bias,
    const float* __restrict__ gamma, const float* __restrict__ beta,
    float* __restrict__ out, __half* __restrict__ hout, int n)
{
    constexpr int NC = KTOT / 32;
    extern __shared__ char sm[];
    float* sbias = (float*)(sm + S_BIAS);
    float* sgam  = (float*)(sm + S_GAM);
    float* sbet  = (float*)(sm + S_BET);
    float* smu   = (float*)(sm + S_MU);
    float* srs   = (float*)(sm + S_RS);
    float* srow  = (float*)(sm + 0);       // 128 x 132 floats, epilogue only

    int tid = threadIdx.x;
    int wid = tid >> 5, lane = tid & 31;
    int g = lane >> 2, t = lane & 3;
    int wm = wid & 3, wn = wid >> 2;
    int m0 = wm * 32, n0 = wn * 64;
    int base = blockIdx.x * 128;

    if (DO_LN && tid < 128) {
        sbias[tid] = __ldg(bias + tid);
        sgam[tid]  = __ldg(gamma + tid);
        sbet[tid]  = __ldg(beta + tid);
    }

    float4 ra[4];
    auto loadAreg = [&](int c) {
        #pragma unroll
        for (int it = 0; it < 4; it++) {
            int idx = tid + it * 256;
            int row = idx >> 3, j4 = idx & 7;
            int grow = base + row;
            int k = c * 32 + j4 * 4;
            float4 v = make_float4(0.f, 0.f, 0.f, 0.f);
            if (grow < n) {
                const float* P = (k < 128) ? (X + (size_t)grow * 128 + k)
                                           : (AGG + (size_t)grow * 128 + (k - 128));
                v = *reinterpret_cast<const float4*>(P);
            }
            v.x = tf32r(v.x); v.y = tf32r(v.y); v.z = tf32r(v.z); v.w = tf32r(v.w);
            ra[it] = v;
        }
    };
    auto storeA = [&](int st) {
        float* As = (float*)(sm + (st ? S_AS1 : S_AS0));
        #pragma unroll
        for (int it = 0; it < 4; it++) {
            int idx = tid + it * 256;
            int row = idx >> 3, j4 = idx & 7;
            *reinterpret_cast<float4*>(&As[row * 36 + j4 * 4]) = ra[it];
        }
    };
    auto preB = [&](int c, int st) {
        uint32_t bbase = smem_u32(sm + (st ? S_BS1 : S_BS0));
        #pragma unroll
        for (int it = 0; it < 4; it++) {
            int idx = tid + it * 256;
            int kk = idx >> 5, j4 = idx & 31;
            cp_async16(bbase + (uint32_t)(kk * 136 + j4 * 4) * 4,
                       Bw + (size_t)(c * 32 + kk) * 128 + j4 * 4);
        }
    };

    float acc[2][8][4];
    #pragma unroll
    for (int mt = 0; mt < 2; mt++)
        #pragma unroll
        for (int nt = 0; nt < 8; nt++)
            #pragma unroll
            for (int cc = 0; cc < 4; cc++) acc[mt][nt][cc] = 0.f;

    preB(0, 0);
    cp_commit();
    loadAreg(0);
    storeA(0);
    cp_wait0();
    __syncthreads();

    #pragma unroll 1
    for (int c = 0; c < NC; c++) {
        int st = c & 1;
        if (c + 1 < NC) {
            preB(c + 1, st ^ 1);
            cp_commit();
            loadAreg(c + 1);
        }
        {
            const float* As = (const float*)(sm + (st ? S_AS1 : S_AS0));
            const float* Bs = (const float*)(sm + (st ? S_BS1 : S_BS0));
            #pragma unroll
            for (int ks = 0; ks < 4; ks++) {
                int k0 = ks * 8;
                u32 af[2][4];
                #pragma unroll
                for (int mt = 0; mt < 2; mt++) {
                    int r = m0 + mt * 16 + g;
                    af[mt][0] = __float_as_uint(As[r * 36 + k0 + t]);
                    af[mt][1] = __float_as_uint(As[(r + 8) * 36 + k0 + t]);
                    af[mt][2] = __float_as_uint(As[r * 36 + k0 + t + 4]);
                    af[mt][3] = __float_as_uint(As[(r + 8) * 36 + k0 + t + 4]);
                }
                #pragma unroll
                for (int nt = 0; nt < 8; nt++) {
                    int ccol = n0 + nt * 8 + g;
                    u32 bf[2];
                    bf[0] = __float_as_uint(Bs[(k0 + t) * 136 + ccol]);
                    bf[1] = __float_as_uint(Bs[(k0 + t + 4) * 136 + ccol]);
                    mma_tf32(acc[0][nt], af[0], bf);
                    mma_tf32(acc[1][nt], af[1], bf);
                }
            }
        }
        if (c + 1 < NC) {
            __syncthreads();
            storeA(st ^ 1);
            cp_wait0();
            __syncthreads();
        }
    }
    __syncthreads();

    // fragments -> srow staging
    #pragma unroll
    for (int mt = 0; mt < 2; mt++) {
        int r0 = m0 + mt * 16 + g;
        #pragma unroll
        for (int nt = 0; nt < 8; nt++) {
            int col = n0 + nt * 8 + 2 * t;
            *reinterpret_cast<float2*>(&srow[r0 * 132 + col]) =
                make_float2(acc[mt][nt][0], acc[mt][nt][1]);
            *reinterpret_cast<float2*>(&srow[(r0 + 8) * 132 + col]) =
                make_float2(acc[mt][nt][2], acc[mt][nt][3]);
        }
    }
    __syncthreads();

    // per-row LN stats (thread = row)
    if (DO_LN && tid < 128) {
        float s1 = 0.f, s2 = 0.f;
        #pragma unroll
        for (int j = 0; j < 128; j += 4) {
            float4 v = *reinterpret_cast<const float4*>(&srow[tid * 132 + j]);
            v.x += sbias[j + 0]; v.y += sbias[j + 1];
            v.z += sbias[j + 2]; v.w += sbias[j + 3];
            *reinterpret_cast<float4*>(&srow[tid * 132 + j]) = v;
            s1 += (v.x + v.y) + (v.z + v.w);
            s2 += (v.x * v.x + v.y * v.y) + (v.z * v.z + v.w * v.w);
        }
        float mu = s1 * (1.0f / 128.0f);
        float var = s2 * (1.0f / 128.0f) - mu * mu;
        smu[tid] = mu;
        srs[tid] = rsqrtf(var + EPS_LN);
    }
    __syncthreads();

    // coalesced stores (+ optional half mirror)
    for (int r = wid; r < 128; r += 8) {
        int row = base + r;
        if (row >= n) continue;
        float4 v = *reinterpret_cast<const float4*>(&srow[r * 132 + lane * 4]);
        if (DO_LN) {
            float mu = smu[r], rs = srs[r];
            float4 gg = *reinterpret_cast<const float4*>(&sgam[lane * 4]);
            float4 ee = *reinterpret_cast<const float4*>(&sbet[lane * 4]);
            v.x = fmaxf((v.x - mu) * rs * gg.x + ee.x, 0.f);
            v.y = fmaxf((v.y - mu) * rs * gg.y + ee.y, 0.f);
            v.z = fmaxf((v.z - mu) * rs * gg.z + ee.z, 0.f);
            v.w = fmaxf((v.w - mu) * rs * gg.w + ee.w, 0.f);
        }
        *reinterpret_cast<float4*>(out + (size_t)row * 128 + lane * 4) = v;
        if (HMODE == 1) {
            *reinterpret_cast<uint2*>(hout + (size_t)row * 128 + lane * 4) = f4_to_h4(v);
        } else if (HMODE == 2) {
            if (lane >= 16)
                *reinterpret_cast<uint2*>(hout + (size_t)row * 64 + (lane - 16) * 4) = f4_to_h4(v);
        }
    }
}

// ---------------- final: out = log_softmax(t2[:, :64] + agg64 + b2) --------
__global__ void __launch_bounds__(256) k_final(
    const float* __restrict__ t2, const float* __restrict__ agg,
    const float* __restrict__ b2, float* __restrict__ out, int n)
{
    int w = (blockIdx.x * 256 + threadIdx.x) >> 5;
    int lane = threadIdx.x & 31;
    if (w >= n) return;
    float va = t2[(size_t)w * 128 + lane]      + agg[(size_t)w * 64 + lane]      + __ldg(&b2[lane]);
    float vb = t2[(size_t)w * 128 + 32 + lane] + agg[(size_t)w * 64 + 32 + lane] + __ldg(&b2[32 + lane]);
    float m = fmaxf(va, vb);
    #pragma unroll
    for (int o = 16; o > 0; o >>= 1)
        m = fmaxf(m, __shfl_xor_sync(0xffffffffu, m, o));
    float se = expf(va - m) + expf(vb - m);
    #pragma unroll
    for (int o = 16; o > 0; o >>= 1)
        se += __shfl_xor_sync(0xffffffffu, se, o);
    float ls = m + logf(se);
    out[(size_t)w * 64 + lane]      = va - ls;
    out[(size_t)w * 64 + 32 + lane] = vb - ls;
}

// ---------------- launcher --------------------------------------------------
extern "C" void kernel_launch(void* const* d_in, const int* in_sizes, int n_in,
                              void* d_out, int out_size)
{
    const float* x   = (const float*)d_in[0];
    const int*  esrc = (const int*)d_in[1];
    const int*  edst = (const int*)d_in[2];
    const float* Wr0 = (const float*)d_in[3];
    const float* Wn0 = (const float*)d_in[4];
    const float* b0  = (const float*)d_in[5];
    const float* g0  = (const float*)d_in[6];
    const float* be0 = (const float*)d_in[7];
    const float* Wr1 = (const float*)d_in[8];
    const float* Wn1 = (const float*)d_in[9];
    const float* b1  = (const float*)d_in[10];
    const float* g1  = (const float*)d_in[11];
    const float* be1 = (const float*)d_in[12];
    const float* Wr2 = (const float*)d_in[13];
    const float* Wn2 = (const float*)d_in[14];
    const float* b2  = (const float*)d_in[15];
    float* out = (float*)d_out;

    int n = in_sizes[0] / 128;
    int E = in_sizes[1];
    if (n > MAXN) n = MAXN;
    if (E > MAXE) E = MAXE;

    int *degi, *off, *cursor, *csr;
    float *rdeg, *agg, *hA, *hB, *Bw0, *Bw1, *Bw2;
    __half *xh, *h0h, *t2h;
    cudaGetSymbolAddress((void**)&degi,   g_degi);
    cudaGetSymbolAddress((void**)&off,    g_off);
    cudaGetSymbolAddress((void**)&cursor, g_cursor);
    cudaGetSymbolAddress((void**)&csr,    g_csr);
    cudaGetSymbolAddress((void**)&rdeg,   g_rdeg);
    cudaGetSymbolAddress((void**)&agg,    g_agg);
    cudaGetSymbolAddress((void**)&hA,     g_hA);
    cudaGetSymbolAddress((void**)&hB,     g_hB);
    cudaGetSymbolAddress((void**)&xh,     g_xh);
    cudaGetSymbolAddress((void**)&h0h,    g_h0h);
    cudaGetSymbolAddress((void**)&t2h,    g_t2h);
    cudaGetSymbolAddress((void**)&Bw0,    g_Bw0);
    cudaGetSymbolAddress((void**)&Bw1,    g_Bw1);
    cudaGetSymbolAddress((void**)&Bw2,    g_Bw2);

    cudaFuncSetAttribute(k_gemm_mma<256, true, 1>,  cudaFuncAttributeMaxDynamicSharedMemorySize, S_TOTAL);
    cudaFuncSetAttribute(k_gemm_mma<256, true, 0>,  cudaFuncAttributeMaxDynamicSharedMemorySize, S_TOTAL);
    cudaFuncSetAttribute(k_gemm_mma<128, false, 2>, cudaFuncAttributeMaxDynamicSharedMemorySize, S_TOTAL);

    int gb = (n + 127) / 128;
    int gw = (n + 7) / 8;

    // CSR build + weight prep + x half mirror
    k_zeroi<<<(n + 255) / 256, 256>>>(degi, n);
    k_count<<<(E + 255) / 256, 256>>>(edst, degi, E);
    k_scan<<<1, 1024>>>(degi, off, cursor, rdeg, n);
    k_fill<<<(E + 255) / 256, 256>>>(esrc, edst, cursor, csr, E);
    k_prep01<<<128, 256>>>(Wr0, Wn0, Bw0);
    k_prep01<<<128, 256>>>(Wr1, Wn1, Bw1);
    k_prep2<<<64, 256>>>(Wr2, Wn2, Bw2);
    k_cvt_half<<<1024, 256>>>(x, xh, (long)n * 32);

    // layer 0: gather x (half), GEMM -> hA (+half mirror h0h)
    k_agg128h<<<gw, 256>>>(xh, csr, off, rdeg, agg, n);
    k_gemm_mma<256, true, 1><<<gb, 256, S_TOTAL>>>(x, agg, Bw0, b0, g0, be0, hA, h0h, n);

    // layer 1: gather h0 (half), GEMM -> hB (no mirror needed)
    k_agg128h<<<gw, 256>>>(h0h, csr, off, rdeg, agg, n);
    k_gemm_mma<256, true, 0><<<gb, 256, S_TOTAL>>>(hA, agg, Bw1, b1, g1, be1, hB, (__half*)0, n);

    // layer 2: t2 = h1 @ [Wr2 | Wn2] (+half mirror of cols 64..127)
    k_gemm_mma<128, false, 2><<<gb, 256, S_TOTAL>>>(hB, hB, Bw2, b2, g0, be0, hA, t2h, n);
    k_agg64h<<<gw, 256>>>(t2h, csr, off, rdeg, agg, n);
    k_final<<<gw, 256>>>(hA, agg, b2, out, n);
}